// round 1
// baseline (speedup 1.0000x reference)
#include <cuda_runtime.h>
#include <cub/cub.cuh>

#define NPTS 4096
#define FEAT 128
#define NEDGE (NPTS - 1)                 // 4095 MST edges
#define NE 8386560                       // NPTS*(NPTS-1)/2 upper-tri entries
#define SEGPAD 8388608                   // 1<<23, padded segment size
#define PADCNT (SEGPAD - NE)             // 2048 sentinel pads per segment
#define TOTKEYS 16777216                 // 2 segments

// ---------------- static device scratch (no allocation allowed) ----------------
__device__ float g_D[2][(size_t)NPTS * NPTS];        // 128 MB distance matrices
__device__ float g_sq[2][NPTS];                      // squared norms
__device__ int g_capBits[2];                         // max distance (float bits, >=0)
__device__ unsigned g_edges[2 * NEDGE];              // MST edges packed (u<<12)|v
__device__ __align__(256) unsigned g_keys[TOTKEYS];  // sort keys (persistence bits | g<<31)
__device__ __align__(256) unsigned g_keysAlt[TOTKEYS];
__device__ __align__(256) unsigned char g_temp[1u << 25];  // 32 MB cub temp
__device__ float g_part[1024];

// ---------------- init: zero caps, write sort-padding sentinels ----------------
__global__ void init_kernel() {
    int t = blockIdx.x * blockDim.x + threadIdx.x;
    if (t < PADCNT) {
        g_keys[NE + t] = 0x7F7FFFFFu;            // > any real key in segment 0
        g_keys[SEGPAD + NE + t] = 0xFFFFFFFFu;   // > any real key in segment 1
    }
    if (t == PADCNT) { g_capBits[0] = 0; g_capBits[1] = 0; }
}

// ---------------- squared norms ----------------
__global__ void sqnorm_kernel(const float* __restrict__ X1, const float* __restrict__ X2) {
    int g = blockIdx.y;
    const float* __restrict__ X = g ? X2 : X1;
    int row = (blockIdx.x * blockDim.x + threadIdx.x) >> 5;
    int lane = threadIdx.x & 31;
    if (row >= NPTS) return;
    float s = 0.f;
#pragma unroll
    for (int c = lane; c < FEAT; c += 32) { float v = X[row * FEAT + c]; s += v * v; }
#pragma unroll
    for (int o = 16; o; o >>= 1) s += __shfl_down_sync(0xffffffffu, s, o);
    if (lane == 0) g_sq[g][row] = s;
}

// ---------------- distance matrix: 64x64 tiles, 4x4 register micro-tiles ----------------
__global__ void dist_kernel(const float* __restrict__ X1, const float* __restrict__ X2) {
    int ti = blockIdx.y, tj = blockIdx.x;
    if (tj < ti) return;  // symmetric: compute upper tiles, mirror the store
    int g = blockIdx.z;
    const float* __restrict__ X = g ? X2 : X1;

    __shared__ __align__(16) float As[16][68];
    __shared__ __align__(16) float Bs[16][68];
    __shared__ float smax[256];

    int tx = threadIdx.x, ty = threadIdx.y;   // 16x16 threads
    int tid = ty * 16 + tx;
    int i0 = ti * 64, j0 = tj * 64;

    float acc[4][4];
#pragma unroll
    for (int r = 0; r < 4; r++)
#pragma unroll
        for (int c = 0; c < 4; c++) acc[r][c] = 0.f;

    for (int k0 = 0; k0 < FEAT; k0 += 16) {
#pragma unroll
        for (int l = 0; l < 4; l++) {
            int lin = tid + l * 256;
            int m = lin >> 4, kk = lin & 15;
            As[kk][m] = X[(i0 + m) * FEAT + k0 + kk];
            Bs[kk][m] = X[(j0 + m) * FEAT + k0 + kk];
        }
        __syncthreads();
#pragma unroll
        for (int k = 0; k < 16; k++) {
            float4 a4 = *(const float4*)&As[k][ty * 4];
            float4 b4 = *(const float4*)&Bs[k][tx * 4];
            float av[4] = {a4.x, a4.y, a4.z, a4.w};
            float bv[4] = {b4.x, b4.y, b4.z, b4.w};
#pragma unroll
            for (int r = 0; r < 4; r++)
#pragma unroll
                for (int c = 0; c < 4; c++) acc[r][c] += av[r] * bv[c];
        }
        __syncthreads();
    }

    float sqi[4], sqj[4];
#pragma unroll
    for (int r = 0; r < 4; r++) {
        sqi[r] = g_sq[g][i0 + ty * 4 + r];
        sqj[r] = g_sq[g][j0 + tx * 4 + r];
    }
    float* Dg = g_D[g];
    float dval[4][4];
    float lmax = 0.f;
#pragma unroll
    for (int r = 0; r < 4; r++) {
#pragma unroll
        for (int c = 0; c < 4; c++) {
            float d2 = sqi[r] + sqj[c] - 2.f * acc[r][c];
            d2 = fmaxf(d2, 0.f);
            float d = (d2 > 1e-12f) ? sqrtf(d2) : 0.f;
            dval[r][c] = d;
            lmax = fmaxf(lmax, d);
        }
        float4 v = make_float4(dval[r][0], dval[r][1], dval[r][2], dval[r][3]);
        *(float4*)&Dg[(size_t)(i0 + ty * 4 + r) * NPTS + j0 + tx * 4] = v;
    }
    if (ti != tj) {
#pragma unroll
        for (int c = 0; c < 4; c++) {
            float4 v = make_float4(dval[0][c], dval[1][c], dval[2][c], dval[3][c]);
            *(float4*)&Dg[(size_t)(j0 + tx * 4 + c) * NPTS + i0 + ty * 4] = v;
        }
    }
    smax[tid] = lmax;
    __syncthreads();
    for (int o = 128; o; o >>= 1) {
        if (tid < o) smax[tid] = fmaxf(smax[tid], smax[tid + o]);
        __syncthreads();
    }
    if (tid == 0) atomicMax(&g_capBits[g], __float_as_int(smax[0]));
}

// ---------------- Prim MST: one block per graph (sequential, round-1 baseline) ----------------
__global__ void __launch_bounds__(1024) prim_kernel() {
    int g = blockIdx.x;
    const float* __restrict__ D = g_D[g];
    __shared__ float mind[NPTS];
    __shared__ unsigned short par[NPTS];
    __shared__ unsigned char vis[NPTS];
    __shared__ unsigned long long sred[32];
    __shared__ int sj;

    int t = threadIdx.x;
    for (int i = t; i < NPTS; i += 1024) {
        mind[i] = D[i];          // row 0
        par[i] = 0;
        vis[i] = (i == 0) ? 1 : 0;
    }
    __syncthreads();
    unsigned* edges = g_edges + g * NEDGE;

    for (int it = 0; it < NEDGE; it++) {
        // ---- argmin over unvisited (pack value bits<<32 | idx: min => smallest idx ties) ----
        unsigned long long best = ~0ULL;
#pragma unroll
        for (int s = 0; s < 4; s++) {
            int i = t + s * 1024;
            if (!vis[i]) {
                unsigned long long k =
                    ((unsigned long long)__float_as_uint(mind[i]) << 32) | (unsigned)i;
                if (k < best) best = k;
            }
        }
#pragma unroll
        for (int o = 16; o; o >>= 1) {
            unsigned long long ov = __shfl_down_sync(0xffffffffu, best, o);
            if (ov < best) best = ov;
        }
        if ((t & 31) == 0) sred[t >> 5] = best;
        __syncthreads();
        if (t < 32) {
            best = sred[t];
#pragma unroll
            for (int o = 16; o; o >>= 1) {
                unsigned long long ov = __shfl_down_sync(0xffffffffu, best, o);
                if (ov < best) best = ov;
            }
            if (t == 0) {
                int j = (int)(unsigned)best;
                sj = j;
                vis[j] = 1;
                edges[it] = ((unsigned)par[j] << 12) | (unsigned)j;
            }
        }
        __syncthreads();
        // ---- relax with row j ----
        int j = sj;
        const float* __restrict__ row = D + (size_t)j * NPTS;
#pragma unroll
        for (int s = 0; s < 4; s++) {
            int i = t + s * 1024;
            if (i != j && !vis[i]) {
                float v = row[i];
                if (v < mind[i]) { mind[i] = v; par[i] = (unsigned short)j; }
            }
        }
        __syncthreads();
    }
}

// ---------------- persistence keys for all upper-tri pairs ----------------
__global__ void pfill_kernel() {
    int g = blockIdx.y;
    size_t idx = (size_t)blockIdx.x * blockDim.x + threadIdx.x;
    if (idx >= (size_t)NPTS * NPTS) return;
    int i = (int)(idx >> 12);
    int j = (int)(idx & (NPTS - 1));
    if (j <= i) return;
    float cap = __int_as_float(g_capBits[g]);
    float d = g_D[g][idx];
    float per = cap - d;  // >= 0 since cap = max(D)
    unsigned k = (unsigned)(((long long)i * (2 * NPTS - i - 1)) >> 1) + (unsigned)(j - i - 1);
    g_keys[(size_t)g * SEGPAD + k] = __float_as_uint(per) | (((unsigned)g) << 31);
}

// ---------------- zero-out tree edges (H0, diagonal points) ----------------
__global__ void fixup_kernel() {
    int e = blockIdx.x * blockDim.x + threadIdx.x;
    if (e >= 2 * NEDGE) return;
    int g = e / NEDGE;
    int i = e % NEDGE;
    unsigned pk = g_edges[g * NEDGE + i];
    int u = (int)(pk >> 12), v = (int)(pk & 4095);
    int a = u < v ? u : v;
    int b = u < v ? v : u;
    unsigned k = (unsigned)(((long long)a * (2 * NPTS - a - 1)) >> 1) + (unsigned)(b - a - 1);
    g_keys[(size_t)g * SEGPAD + k] = ((unsigned)g) << 31;  // persistence 0.0
}

// ---------------- Wasserstein sum over the two sorted segments ----------------
__global__ void wsum1_kernel(const unsigned* __restrict__ keys) {
    __shared__ float sh[256];
    float s = 0.f;
    for (size_t k = (size_t)blockIdx.x * blockDim.x + threadIdx.x; k < NE;
         k += (size_t)gridDim.x * blockDim.x) {
        float a = __uint_as_float(keys[k]);
        float b = __uint_as_float(keys[SEGPAD + k] & 0x7FFFFFFFu);
        s += fabsf(a - b);
    }
    sh[threadIdx.x] = s;
    __syncthreads();
    for (int o = 128; o; o >>= 1) {
        if (threadIdx.x < o) sh[threadIdx.x] += sh[threadIdx.x + o];
        __syncthreads();
    }
    if (threadIdx.x == 0) g_part[blockIdx.x] = sh[0];
}

__global__ void wsum2_kernel(float* __restrict__ out) {
    __shared__ double sh[1024];
    sh[threadIdx.x] = (double)g_part[threadIdx.x];
    __syncthreads();
    for (int o = 512; o; o >>= 1) {
        if (threadIdx.x < o) sh[threadIdx.x] += sh[threadIdx.x + o];
        __syncthreads();
    }
    if (threadIdx.x == 0) out[0] = (float)(1.0 * sh[0]);  // WEIGHT = 1.0
}

// ---------------- launch ----------------
extern "C" void kernel_launch(void* const* d_in, const int* in_sizes, int n_in,
                              void* d_out, int out_size) {
    const float* X1 = (const float*)d_in[0];
    const float* X2 = (const float*)d_in[2];
    float* out = (float*)d_out;

    init_kernel<<<(PADCNT + 256) / 256, 256>>>();
    sqnorm_kernel<<<dim3(NPTS / 8, 2), 256>>>(X1, X2);
    dist_kernel<<<dim3(64, 64, 2), dim3(16, 16)>>>(X1, X2);
    prim_kernel<<<2, 1024>>>();
    pfill_kernel<<<dim3((NPTS * NPTS) / 256, 2), 256>>>();
    fixup_kernel<<<(2 * NEDGE + 255) / 256, 256>>>();

    unsigned *keys, *alt;
    void* tempp;
    cudaGetSymbolAddress((void**)&keys, g_keys);
    cudaGetSymbolAddress((void**)&alt, g_keysAlt);
    cudaGetSymbolAddress(&tempp, g_temp);

    cub::DoubleBuffer<unsigned> db(keys, alt);
    size_t bytes = 0;
    cub::DeviceRadixSort::SortKeys(nullptr, bytes, db, TOTKEYS, 0, 32, (cudaStream_t)0);
    // g_temp is 32 MB; required temp for 16.8M u32 keys is far below that.
    cub::DeviceRadixSort::SortKeys(tempp, bytes, db, TOTKEYS, 0, 32, (cudaStream_t)0);

    const unsigned* sorted = db.Current();
    wsum1_kernel<<<1024, 256>>>(sorted);
    wsum2_kernel<<<1, 1024>>>(out);
}

// round 2
// speedup vs baseline: 1.0028x; 1.0028x over previous
#include <cuda_runtime.h>
#include <cub/cub.cuh>

#define NPTS 4096
#define FEAT 128
#define NEDGE (NPTS - 1)                 // 4095 MST edges
#define NE 8386560                       // NPTS*(NPTS-1)/2 upper-tri entries
#define SEGPAD 8388608                   // 1<<23, padded segment size
#define PADCNT (SEGPAD - NE)             // 2048 sentinel pads per segment
#define TOTKEYS 16777216                 // 2 segments

// ---------------- static device scratch (no allocation allowed) ----------------
__device__ float g_D[2][(size_t)NPTS * NPTS];        // 128 MB distance matrices
__device__ float g_sq[2][NPTS];                      // squared norms
__device__ int g_capBits[2];                         // max distance (float bits, >=0)
__device__ unsigned g_edges[2 * NEDGE];              // MST edges packed (u<<12)|v
__device__ __align__(256) unsigned g_keys[TOTKEYS];  // sort keys (persistence bits | g<<31)
__device__ __align__(256) unsigned g_keysAlt[TOTKEYS];
__device__ __align__(256) unsigned char g_temp[1u << 25];  // 32 MB cub temp
__device__ float g_part[1024];

// ---------------- init: zero caps, write sort-padding sentinels ----------------
__global__ void init_kernel() {
    int t = blockIdx.x * blockDim.x + threadIdx.x;
    if (t < PADCNT) {
        g_keys[NE + t] = 0x7F7FFFFFu;            // > any real key in segment 0
        g_keys[SEGPAD + NE + t] = 0xFFFFFFFFu;   // > any real key in segment 1
    }
    if (t == PADCNT) { g_capBits[0] = 0; g_capBits[1] = 0; }
}

// ---------------- squared norms ----------------
__global__ void sqnorm_kernel(const float* __restrict__ X1, const float* __restrict__ X2) {
    int g = blockIdx.y;
    const float* __restrict__ X = g ? X2 : X1;
    int row = (blockIdx.x * blockDim.x + threadIdx.x) >> 5;
    int lane = threadIdx.x & 31;
    if (row >= NPTS) return;
    float s = 0.f;
#pragma unroll
    for (int c = lane; c < FEAT; c += 32) { float v = X[row * FEAT + c]; s += v * v; }
#pragma unroll
    for (int o = 16; o; o >>= 1) s += __shfl_down_sync(0xffffffffu, s, o);
    if (lane == 0) g_sq[g][row] = s;
}

// ---------------- distance matrix: 64x64 tiles, 4x4 register micro-tiles ----------------
__global__ void dist_kernel(const float* __restrict__ X1, const float* __restrict__ X2) {
    int ti = blockIdx.y, tj = blockIdx.x;
    if (tj < ti) return;  // symmetric: compute upper tiles, mirror the store
    int g = blockIdx.z;
    const float* __restrict__ X = g ? X2 : X1;

    __shared__ __align__(16) float As[16][68];
    __shared__ __align__(16) float Bs[16][68];
    __shared__ float smax[256];

    int tx = threadIdx.x, ty = threadIdx.y;   // 16x16 threads
    int tid = ty * 16 + tx;
    int i0 = ti * 64, j0 = tj * 64;

    float acc[4][4];
#pragma unroll
    for (int r = 0; r < 4; r++)
#pragma unroll
        for (int c = 0; c < 4; c++) acc[r][c] = 0.f;

    for (int k0 = 0; k0 < FEAT; k0 += 16) {
#pragma unroll
        for (int l = 0; l < 4; l++) {
            int lin = tid + l * 256;
            int m = lin >> 4, kk = lin & 15;
            As[kk][m] = X[(i0 + m) * FEAT + k0 + kk];
            Bs[kk][m] = X[(j0 + m) * FEAT + k0 + kk];
        }
        __syncthreads();
#pragma unroll
        for (int k = 0; k < 16; k++) {
            float4 a4 = *(const float4*)&As[k][ty * 4];
            float4 b4 = *(const float4*)&Bs[k][tx * 4];
            float av[4] = {a4.x, a4.y, a4.z, a4.w};
            float bv[4] = {b4.x, b4.y, b4.z, b4.w};
#pragma unroll
            for (int r = 0; r < 4; r++)
#pragma unroll
                for (int c = 0; c < 4; c++) acc[r][c] += av[r] * bv[c];
        }
        __syncthreads();
    }

    float sqi[4], sqj[4];
#pragma unroll
    for (int r = 0; r < 4; r++) {
        sqi[r] = g_sq[g][i0 + ty * 4 + r];
        sqj[r] = g_sq[g][j0 + tx * 4 + r];
    }
    float* Dg = g_D[g];
    float dval[4][4];
    float lmax = 0.f;
#pragma unroll
    for (int r = 0; r < 4; r++) {
#pragma unroll
        for (int c = 0; c < 4; c++) {
            float d2 = sqi[r] + sqj[c] - 2.f * acc[r][c];
            d2 = fmaxf(d2, 0.f);
            float d = (d2 > 1e-12f) ? sqrtf(d2) : 0.f;
            dval[r][c] = d;
            lmax = fmaxf(lmax, d);
        }
        float4 v = make_float4(dval[r][0], dval[r][1], dval[r][2], dval[r][3]);
        *(float4*)&Dg[(size_t)(i0 + ty * 4 + r) * NPTS + j0 + tx * 4] = v;
    }
    if (ti != tj) {
#pragma unroll
        for (int c = 0; c < 4; c++) {
            float4 v = make_float4(dval[0][c], dval[1][c], dval[2][c], dval[3][c]);
            *(float4*)&Dg[(size_t)(j0 + tx * 4 + c) * NPTS + i0 + ty * 4] = v;
        }
    }
    smax[tid] = lmax;
    __syncthreads();
    for (int o = 128; o; o >>= 1) {
        if (tid < o) smax[tid] = fmaxf(smax[tid], smax[tid + o]);
        __syncthreads();
    }
    if (tid == 0) atomicMax(&g_capBits[g], __float_as_int(smax[0]));
}

// ---------------- Prim MST: one block per graph (sequential, round-1 baseline) ----------------
__global__ void __launch_bounds__(1024) prim_kernel() {
    int g = blockIdx.x;
    const float* __restrict__ D = g_D[g];
    __shared__ float mind[NPTS];
    __shared__ unsigned short par[NPTS];
    __shared__ unsigned char vis[NPTS];
    __shared__ unsigned long long sred[32];
    __shared__ int sj;

    int t = threadIdx.x;
    for (int i = t; i < NPTS; i += 1024) {
        mind[i] = D[i];          // row 0
        par[i] = 0;
        vis[i] = (i == 0) ? 1 : 0;
    }
    __syncthreads();
    unsigned* edges = g_edges + g * NEDGE;

    for (int it = 0; it < NEDGE; it++) {
        // ---- argmin over unvisited (pack value bits<<32 | idx: min => smallest idx ties) ----
        unsigned long long best = ~0ULL;
#pragma unroll
        for (int s = 0; s < 4; s++) {
            int i = t + s * 1024;
            if (!vis[i]) {
                unsigned long long k =
                    ((unsigned long long)__float_as_uint(mind[i]) << 32) | (unsigned)i;
                if (k < best) best = k;
            }
        }
#pragma unroll
        for (int o = 16; o; o >>= 1) {
            unsigned long long ov = __shfl_down_sync(0xffffffffu, best, o);
            if (ov < best) best = ov;
        }
        if ((t & 31) == 0) sred[t >> 5] = best;
        __syncthreads();
        if (t < 32) {
            best = sred[t];
#pragma unroll
            for (int o = 16; o; o >>= 1) {
                unsigned long long ov = __shfl_down_sync(0xffffffffu, best, o);
                if (ov < best) best = ov;
            }
            if (t == 0) {
                int j = (int)(unsigned)best;
                sj = j;
                vis[j] = 1;
                edges[it] = ((unsigned)par[j] << 12) | (unsigned)j;
            }
        }
        __syncthreads();
        // ---- relax with row j ----
        int j = sj;
        const float* __restrict__ row = D + (size_t)j * NPTS;
#pragma unroll
        for (int s = 0; s < 4; s++) {
            int i = t + s * 1024;
            if (i != j && !vis[i]) {
                float v = row[i];
                if (v < mind[i]) { mind[i] = v; par[i] = (unsigned short)j; }
            }
        }
        __syncthreads();
    }
}

// ---------------- persistence keys for all upper-tri pairs ----------------
__global__ void pfill_kernel() {
    int g = blockIdx.y;
    size_t idx = (size_t)blockIdx.x * blockDim.x + threadIdx.x;
    if (idx >= (size_t)NPTS * NPTS) return;
    int i = (int)(idx >> 12);
    int j = (int)(idx & (NPTS - 1));
    if (j <= i) return;
    float cap = __int_as_float(g_capBits[g]);
    float d = g_D[g][idx];
    float per = cap - d;  // >= 0 since cap = max(D)
    unsigned k = (unsigned)(((long long)i * (2 * NPTS - i - 1)) >> 1) + (unsigned)(j - i - 1);
    g_keys[(size_t)g * SEGPAD + k] = __float_as_uint(per) | (((unsigned)g) << 31);
}

// ---------------- zero-out tree edges (H0, diagonal points) ----------------
__global__ void fixup_kernel() {
    int e = blockIdx.x * blockDim.x + threadIdx.x;
    if (e >= 2 * NEDGE) return;
    int g = e / NEDGE;
    int i = e % NEDGE;
    unsigned pk = g_edges[g * NEDGE + i];
    int u = (int)(pk >> 12), v = (int)(pk & 4095);
    int a = u < v ? u : v;
    int b = u < v ? v : u;
    unsigned k = (unsigned)(((long long)a * (2 * NPTS - a - 1)) >> 1) + (unsigned)(b - a - 1);
    g_keys[(size_t)g * SEGPAD + k] = ((unsigned)g) << 31;  // persistence 0.0
}

// ---------------- Wasserstein sum over the two sorted segments ----------------
__global__ void wsum1_kernel(const unsigned* __restrict__ keys) {
    __shared__ float sh[256];
    float s = 0.f;
    for (size_t k = (size_t)blockIdx.x * blockDim.x + threadIdx.x; k < NE;
         k += (size_t)gridDim.x * blockDim.x) {
        float a = __uint_as_float(keys[k]);
        float b = __uint_as_float(keys[SEGPAD + k] & 0x7FFFFFFFu);
        s += fabsf(a - b);
    }
    sh[threadIdx.x] = s;
    __syncthreads();
    for (int o = 128; o; o >>= 1) {
        if (threadIdx.x < o) sh[threadIdx.x] += sh[threadIdx.x + o];
        __syncthreads();
    }
    if (threadIdx.x == 0) g_part[blockIdx.x] = sh[0];
}

__global__ void wsum2_kernel(float* __restrict__ out) {
    __shared__ double sh[1024];
    sh[threadIdx.x] = (double)g_part[threadIdx.x];
    __syncthreads();
    for (int o = 512; o; o >>= 1) {
        if (threadIdx.x < o) sh[threadIdx.x] += sh[threadIdx.x + o];
        __syncthreads();
    }
    if (threadIdx.x == 0) out[0] = (float)(1.0 * sh[0]);  // WEIGHT = 1.0
}

// ---------------- launch ----------------
extern "C" void kernel_launch(void* const* d_in, const int* in_sizes, int n_in,
                              void* d_out, int out_size) {
    const float* X1 = (const float*)d_in[0];
    const float* X2 = (const float*)d_in[2];
    float* out = (float*)d_out;

    init_kernel<<<(PADCNT + 256) / 256, 256>>>();
    sqnorm_kernel<<<dim3(NPTS / 8, 2), 256>>>(X1, X2);
    dist_kernel<<<dim3(64, 64, 2), dim3(16, 16)>>>(X1, X2);
    prim_kernel<<<2, 1024>>>();
    pfill_kernel<<<dim3((NPTS * NPTS) / 256, 2), 256>>>();
    fixup_kernel<<<(2 * NEDGE + 255) / 256, 256>>>();

    unsigned *keys, *alt;
    void* tempp;
    cudaGetSymbolAddress((void**)&keys, g_keys);
    cudaGetSymbolAddress((void**)&alt, g_keysAlt);
    cudaGetSymbolAddress(&tempp, g_temp);

    cub::DoubleBuffer<unsigned> db(keys, alt);
    size_t bytes = 0;
    cub::DeviceRadixSort::SortKeys(nullptr, bytes, db, TOTKEYS, 0, 32, (cudaStream_t)0);
    // g_temp is 32 MB; required temp for 16.8M u32 keys is far below that.
    cub::DeviceRadixSort::SortKeys(tempp, bytes, db, TOTKEYS, 0, 32, (cudaStream_t)0);

    const unsigned* sorted = db.Current();
    wsum1_kernel<<<1024, 256>>>(sorted);
    wsum2_kernel<<<1, 1024>>>(out);
}

// round 3
// speedup vs baseline: 14.1247x; 14.0849x over previous
#include <cuda_runtime.h>
#include <cub/cub.cuh>

#define NPTS 4096
#define FEAT 128
#define NEDGE (NPTS - 1)                 // 4095 MST edges
#define NE 8386560                       // NPTS*(NPTS-1)/2 upper-tri entries
#define SEGPAD 8388608                   // 1<<23, padded segment size
#define PADCNT (SEGPAD - NE)             // 2048 sentinel pads per segment
#define TOTKEYS 16777216                 // 2 segments
#define SENTK 0xFFFFFFFFFFFFFFFFULL
#define BORUVKA_ROUNDS 14

// ---------------- static device scratch (no allocation allowed) ----------------
__device__ float g_D[2][(size_t)NPTS * NPTS];        // 128 MB distance matrices
__device__ float g_sq[2][NPTS];                      // squared norms
__device__ int g_capBits[2];                         // max distance (float bits, >=0)
__device__ unsigned g_edges[2 * NEDGE];              // MST edges canonical (a<<12)|b
__device__ unsigned long long g_best[2][NPTS];       // per-component best edge key
__device__ int g_comp[2][NPTS];                      // component labels (rep vertex)
__device__ int g_ncomp[2];
__device__ int g_necnt[2];
__device__ __align__(256) unsigned g_keys[TOTKEYS];  // sort keys (persistence bits | g<<31)
__device__ __align__(256) unsigned g_keysAlt[TOTKEYS];
__device__ __align__(256) unsigned char g_temp[1u << 25];  // 32 MB cub temp
__device__ float g_part[1024];

// ---------------- init: caps, MST state, sort-padding sentinels ----------------
__global__ void init_kernel() {
    int t = blockIdx.x * blockDim.x + threadIdx.x;
    if (t < PADCNT) {
        g_keys[NE + t] = 0x7F7FFFFFu;            // > any real key in segment 0
        g_keys[SEGPAD + NE + t] = 0xFFFFFFFFu;   // > any real key in segment 1
    }
    if (t < NPTS) {
        g_comp[0][t] = t; g_comp[1][t] = t;
        g_best[0][t] = SENTK; g_best[1][t] = SENTK;
    }
    if (t == 0) {
        g_capBits[0] = 0; g_capBits[1] = 0;
        g_ncomp[0] = NPTS; g_ncomp[1] = NPTS;
        g_necnt[0] = 0; g_necnt[1] = 0;
    }
}

// ---------------- squared norms ----------------
__global__ void sqnorm_kernel(const float* __restrict__ X1, const float* __restrict__ X2) {
    int g = blockIdx.y;
    const float* __restrict__ X = g ? X2 : X1;
    int row = (blockIdx.x * blockDim.x + threadIdx.x) >> 5;
    int lane = threadIdx.x & 31;
    if (row >= NPTS) return;
    float s = 0.f;
#pragma unroll
    for (int c = lane; c < FEAT; c += 32) { float v = X[row * FEAT + c]; s += v * v; }
#pragma unroll
    for (int o = 16; o; o >>= 1) s += __shfl_down_sync(0xffffffffu, s, o);
    if (lane == 0) g_sq[g][row] = s;
}

// ---------------- distance matrix: 64x64 tiles, 4x4 register micro-tiles ----------------
__global__ void dist_kernel(const float* __restrict__ X1, const float* __restrict__ X2) {
    int ti = blockIdx.y, tj = blockIdx.x;
    if (tj < ti) return;  // symmetric: compute upper tiles, mirror the store
    int g = blockIdx.z;
    const float* __restrict__ X = g ? X2 : X1;

    __shared__ __align__(16) float As[16][68];
    __shared__ __align__(16) float Bs[16][68];
    __shared__ float smax[256];

    int tx = threadIdx.x, ty = threadIdx.y;   // 16x16 threads
    int tid = ty * 16 + tx;
    int i0 = ti * 64, j0 = tj * 64;

    float acc[4][4];
#pragma unroll
    for (int r = 0; r < 4; r++)
#pragma unroll
        for (int c = 0; c < 4; c++) acc[r][c] = 0.f;

    for (int k0 = 0; k0 < FEAT; k0 += 16) {
#pragma unroll
        for (int l = 0; l < 4; l++) {
            int lin = tid + l * 256;
            int m = lin >> 4, kk = lin & 15;
            As[kk][m] = X[(i0 + m) * FEAT + k0 + kk];
            Bs[kk][m] = X[(j0 + m) * FEAT + k0 + kk];
        }
        __syncthreads();
#pragma unroll
        for (int k = 0; k < 16; k++) {
            float4 a4 = *(const float4*)&As[k][ty * 4];
            float4 b4 = *(const float4*)&Bs[k][tx * 4];
            float av[4] = {a4.x, a4.y, a4.z, a4.w};
            float bv[4] = {b4.x, b4.y, b4.z, b4.w};
#pragma unroll
            for (int r = 0; r < 4; r++)
#pragma unroll
                for (int c = 0; c < 4; c++) acc[r][c] += av[r] * bv[c];
        }
        __syncthreads();
    }

    float sqi[4], sqj[4];
#pragma unroll
    for (int r = 0; r < 4; r++) {
        sqi[r] = g_sq[g][i0 + ty * 4 + r];
        sqj[r] = g_sq[g][j0 + tx * 4 + r];
    }
    float* Dg = g_D[g];
    float dval[4][4];
    float lmax = 0.f;
#pragma unroll
    for (int r = 0; r < 4; r++) {
#pragma unroll
        for (int c = 0; c < 4; c++) {
            float d2 = sqi[r] + sqj[c] - 2.f * acc[r][c];
            d2 = fmaxf(d2, 0.f);
            float d = (d2 > 1e-12f) ? sqrtf(d2) : 0.f;
            dval[r][c] = d;
            lmax = fmaxf(lmax, d);
        }
        float4 v = make_float4(dval[r][0], dval[r][1], dval[r][2], dval[r][3]);
        *(float4*)&Dg[(size_t)(i0 + ty * 4 + r) * NPTS + j0 + tx * 4] = v;
    }
    if (ti != tj) {
#pragma unroll
        for (int c = 0; c < 4; c++) {
            float4 v = make_float4(dval[0][c], dval[1][c], dval[2][c], dval[3][c]);
            *(float4*)&Dg[(size_t)(j0 + tx * 4 + c) * NPTS + i0 + ty * 4] = v;
        }
    }
    smax[tid] = lmax;
    __syncthreads();
    for (int o = 128; o; o >>= 1) {
        if (tid < o) smax[tid] = fmaxf(smax[tid], smax[tid + o]);
        __syncthreads();
    }
    if (tid == 0) atomicMax(&g_capBits[g], __float_as_int(smax[0]));
}

// ---------------- Boruvka phase 1: per-vertex min outgoing edge ----------------
// 8 rows per block (warp per row); grid (512, 2). Early-exit when converged.
__global__ void __launch_bounds__(256) bmin_kernel() {
    int g = blockIdx.y;
    if (g_ncomp[g] <= 1) return;
    __shared__ int scomp[NPTS];
    int t = threadIdx.x;
    for (int i = t; i < NPTS; i += 256) scomp[i] = g_comp[g][i];
    __syncthreads();

    int warp = t >> 5, lane = t & 31;
    int r = blockIdx.x * 8 + warp;
    int myc = scomp[r];
    const float* __restrict__ row = g_D[g] + (size_t)r * NPTS;
    unsigned long long best = SENTK;
    for (int j0 = lane * 4; j0 < NPTS; j0 += 128) {
        float4 v = *(const float4*)(row + j0);
        float dv[4] = {v.x, v.y, v.z, v.w};
#pragma unroll
        for (int u = 0; u < 4; u++) {
            int j = j0 + u;
            if (scomp[j] != myc) {
                int a = min(r, j), b = max(r, j);
                unsigned long long k =
                    ((unsigned long long)__float_as_uint(dv[u]) << 24) |
                    (unsigned)((a << 12) | b);
                if (k < best) best = k;
            }
        }
    }
#pragma unroll
    for (int o = 16; o; o >>= 1) {
        unsigned long long ov = __shfl_down_sync(0xffffffffu, best, o);
        if (ov < best) best = ov;
    }
    if (lane == 0 && best != SENTK) atomicMin(&g_best[g][myc], best);
}

// ---------------- Boruvka phase 2: merge components (1 block/graph) ----------------
__global__ void __launch_bounds__(1024) bmerge_kernel() {
    int g = blockIdx.x;
    if (g_ncomp[g] <= 1) return;
    __shared__ int par[NPTS];
    __shared__ int scnt;
    int t = threadIdx.x;
    for (int i = t; i < NPTS; i += 1024) par[i] = i;
    if (t == 0) scnt = 0;
    __syncthreads();

    // link each component to its best-edge partner; dedup paired picks
    for (int v = t; v < NPTS; v += 1024) {
        unsigned long long bk = g_best[g][v];
        if (bk != SENTK) {
            unsigned eid = (unsigned)(bk & 0xFFFFFFu);
            int a = (int)(eid >> 12), b = (int)(eid & 4095);
            int ca = g_comp[g][a], cb = g_comp[g][b];
            int other = (ca == v) ? cb : ca;
            bool add = !(g_best[g][other] == bk && other < v);
            if (add) {
                int slot = atomicAdd(&g_necnt[g], 1);
                if (slot < NEDGE) g_edges[g * NEDGE + slot] = eid;
            }
            par[v] = other;
        }
    }
    __syncthreads();
    // break 2-cycles: smaller id becomes root
    for (int v = t; v < NPTS; v += 1024) {
        int p = par[v];
        if (p != v && par[p] == v && v < p) par[v] = v;
    }
    __syncthreads();
    // pointer jumping to flatten (monotone; races benign)
    for (int it = 0; it < 13; it++) {
        for (int v = t; v < NPTS; v += 1024) par[v] = par[par[v]];
        __syncthreads();
    }
    // relabel all vertices, reset bests
    for (int i = t; i < NPTS; i += 1024) {
        g_comp[g][i] = par[g_comp[g][i]];
        g_best[g][i] = SENTK;
    }
    __syncthreads();
    // count components
    int local = 0;
    for (int i = t; i < NPTS; i += 1024)
        if (g_comp[g][i] == i) local++;
    atomicAdd(&scnt, local);
    __syncthreads();
    if (t == 0) g_ncomp[g] = scnt;
}

// ---------------- persistence keys for all upper-tri pairs ----------------
__global__ void pfill_kernel() {
    int g = blockIdx.y;
    size_t idx = (size_t)blockIdx.x * blockDim.x + threadIdx.x;
    if (idx >= (size_t)NPTS * NPTS) return;
    int i = (int)(idx >> 12);
    int j = (int)(idx & (NPTS - 1));
    if (j <= i) return;
    float cap = __int_as_float(g_capBits[g]);
    float d = g_D[g][idx];
    float per = cap - d;  // >= 0 since cap = max(D)
    unsigned k = (unsigned)(((long long)i * (2 * NPTS - i - 1)) >> 1) + (unsigned)(j - i - 1);
    g_keys[(size_t)g * SEGPAD + k] = __float_as_uint(per) | (((unsigned)g) << 31);
}

// ---------------- zero-out tree edges (H0, diagonal points) ----------------
__global__ void fixup_kernel() {
    int e = blockIdx.x * blockDim.x + threadIdx.x;
    if (e >= 2 * NEDGE) return;
    int g = e / NEDGE;
    int i = e % NEDGE;
    unsigned pk = g_edges[g * NEDGE + i];
    int u = (int)(pk >> 12), v = (int)(pk & 4095);
    int a = u < v ? u : v;
    int b = u < v ? v : u;
    unsigned k = (unsigned)(((long long)a * (2 * NPTS - a - 1)) >> 1) + (unsigned)(b - a - 1);
    g_keys[(size_t)g * SEGPAD + k] = ((unsigned)g) << 31;  // persistence 0.0
}

// ---------------- Wasserstein sum over the two sorted segments ----------------
__global__ void wsum1_kernel(const unsigned* __restrict__ keys) {
    __shared__ float sh[256];
    float s = 0.f;
    for (size_t k = (size_t)blockIdx.x * blockDim.x + threadIdx.x; k < NE;
         k += (size_t)gridDim.x * blockDim.x) {
        float a = __uint_as_float(keys[k]);
        float b = __uint_as_float(keys[SEGPAD + k] & 0x7FFFFFFFu);
        s += fabsf(a - b);
    }
    sh[threadIdx.x] = s;
    __syncthreads();
    for (int o = 128; o; o >>= 1) {
        if (threadIdx.x < o) sh[threadIdx.x] += sh[threadIdx.x + o];
        __syncthreads();
    }
    if (threadIdx.x == 0) g_part[blockIdx.x] = sh[0];
}

__global__ void wsum2_kernel(float* __restrict__ out) {
    __shared__ double sh[1024];
    sh[threadIdx.x] = (double)g_part[threadIdx.x];
    __syncthreads();
    for (int o = 512; o; o >>= 1) {
        if (threadIdx.x < o) sh[threadIdx.x] += sh[threadIdx.x + o];
        __syncthreads();
    }
    if (threadIdx.x == 0) out[0] = (float)(1.0 * sh[0]);  // WEIGHT = 1.0
}

// ---------------- launch ----------------
extern "C" void kernel_launch(void* const* d_in, const int* in_sizes, int n_in,
                              void* d_out, int out_size) {
    const float* X1 = (const float*)d_in[0];
    const float* X2 = (const float*)d_in[2];
    float* out = (float*)d_out;

    init_kernel<<<(NPTS > PADCNT ? NPTS : PADCNT + 256) / 256 + 1, 256>>>();
    sqnorm_kernel<<<dim3(NPTS / 8, 2), 256>>>(X1, X2);
    dist_kernel<<<dim3(64, 64, 2), dim3(16, 16)>>>(X1, X2);

    for (int r = 0; r < BORUVKA_ROUNDS; r++) {
        bmin_kernel<<<dim3(NPTS / 8, 2), 256>>>();
        bmerge_kernel<<<2, 1024>>>();
    }

    pfill_kernel<<<dim3((NPTS * NPTS) / 256, 2), 256>>>();
    fixup_kernel<<<(2 * NEDGE + 255) / 256, 256>>>();

    unsigned *keys, *alt;
    void* tempp;
    cudaGetSymbolAddress((void**)&keys, g_keys);
    cudaGetSymbolAddress((void**)&alt, g_keysAlt);
    cudaGetSymbolAddress(&tempp, g_temp);

    cub::DoubleBuffer<unsigned> db(keys, alt);
    size_t bytes = 0;
    cub::DeviceRadixSort::SortKeys(nullptr, bytes, db, TOTKEYS, 0, 32, (cudaStream_t)0);
    cub::DeviceRadixSort::SortKeys(tempp, bytes, db, TOTKEYS, 0, 32, (cudaStream_t)0);

    const unsigned* sorted = db.Current();
    wsum1_kernel<<<1024, 256>>>(sorted);
    wsum2_kernel<<<1, 1024>>>(out);
}